// round 13
// baseline (speedup 1.0000x reference)
#include <cuda_runtime.h>
#include <math_constants.h>

// Problem shape
#define BB 8
#define HH 3
#define PP 4096
#define NPTS (BB * PP)
#define CH 256                   // chunk size (both I and J side)
#define NCH (PP / CH)            // 16 chunks per batch
#define NPAIR (CH / 2)           // 128 packed J-pairs = TP
#define TP 128                   // threads per block (4 warps)
#define IK 2                     // I-points per thread (per warp: 64)
#define BLKB (NCH * (NCH + 1) / 2)   // 136 triangular blocks per batch
#define NBLK 128

// per-(head,point) min as uint bits of nonneg float; reset to 0x7F7F7F7F
__device__ unsigned int g_minbits[HH * NPTS];
__device__ float g_partial[NBLK];

// ---- f32x2 helpers ---------------------------------------------------------
__device__ __forceinline__ unsigned long long pack2(float lo, float hi) {
    unsigned long long d;
    asm("mov.b64 %0, {%1, %2};" : "=l"(d) : "f"(lo), "f"(hi));
    return d;
}
__device__ __forceinline__ unsigned long long fma2(unsigned long long a,
                                                   unsigned long long b,
                                                   unsigned long long c) {
    unsigned long long d;
    asm("fma.rn.f32x2 %0, %1, %2, %3;" : "=l"(d) : "l"(a), "l"(b), "l"(c));
    return d;
}
__device__ __forceinline__ unsigned long long add2(unsigned long long a,
                                                   unsigned long long b) {
    unsigned long long d;
    asm("add.rn.f32x2 %0, %1, %2;" : "=l"(d) : "l"(a), "l"(b));
    return d;
}
__device__ __forceinline__ void unpack2(unsigned long long t, float& lo, float& hi) {
    asm("mov.b64 {%0, %1}, %2;" : "=f"(lo), "=f"(hi) : "l"(t));
}

// normalized plane normals + offset for batch b
__device__ __forceinline__ void load_normals(const float* __restrict__ planes,
                                             int b, float nx[HH], float ny[HH],
                                             float nz[HH], float nc[HH]) {
#pragma unroll
    for (int h = 0; h < HH; h++) {
        const float* pl = planes + (b * HH + h) * 4;
        float x = pl[0], y = pl[1], z = pl[2];
        float nn = x * x + y * y + z * z;
        float inv = rsqrtf(nn);
        inv = inv * (1.5f - 0.5f * nn * inv * inv);
        nx[h] = x * inv; ny[h] = y * inv; nz[h] = z * inv; nc[h] = pl[3];
    }
}

// ---------------------------------------------------------------------------
// Symmetric chamfer, register-resident J side.
// Block = (chunk i, chunk j), i<=j, both 256 points. Lane permanently owns
// 4 packed J-slots (data + J-mins in registers). The I-side (2 points per
// lane: 14 u64 constants + 6 min floats) ring-shuffles through the warp over
// 32 rotations, so every I-point meets every J-slot. Zero smem in main loop.
// ---------------------------------------------------------------------------
__global__ __launch_bounds__(TP)
void chamfer_kernel(const float* __restrict__ planes,
                    const float* __restrict__ pts) {
    __shared__ ulonglong2         stA[NPAIR];  // (x0,x1),(y0,y1)
    __shared__ ulonglong2         stB[NPAIR];  // (z0,z1),(w0,w1)
    __shared__ ulonglong2         stC[NPAIR];  // (2d0q0,2d0q1),(2d1q0,2d1q1)
    __shared__ unsigned long long stD[NPAIR];  // (2d2q0,2d2q1)
    __shared__ float sJm[4][32][24];           // final J merge [warp][lane][vals]

    const int t    = threadIdx.x;
    const int lane = t & 31;
    const int w    = t >> 5;
    const int b    = blockIdx.z;

    // triangular decode: (ci, cj) with ci <= cj
    int f = blockIdx.x, ci = 0;
    while (f >= NCH - ci) { f -= NCH - ci; ci++; }
    const int cj = ci + f;

    float nx[HH], ny[HH], nz[HH], nc[HH];
    load_normals(planes, b, nx, ny, nz, nc);

    // ---- stage J-chunk cj into smem (one pair per thread) ----
    {
        const float* q = pts + (b * PP + cj * CH + 2 * t) * 3;
        float x0 = q[0], y0 = q[1], z0 = q[2];
        float x1 = q[3], y1 = q[4], z1 = q[5];
        float w0 = x0 * x0 + y0 * y0 + z0 * z0;
        float w1 = x1 * x1 + y1 * y1 + z1 * z1;
        float d0[HH], d1[HH];
#pragma unroll
        for (int h = 0; h < HH; h++) {
            d0[h] = 2.f * (nx[h] * x0 + ny[h] * y0 + nz[h] * z0 + nc[h]);
            d1[h] = 2.f * (nx[h] * x1 + ny[h] * y1 + nz[h] * z1 + nc[h]);
        }
        ulonglong2 A, B, C;
        A.x = pack2(x0, x1);     A.y = pack2(y0, y1);
        B.x = pack2(z0, z1);     B.y = pack2(w0, w1);
        C.x = pack2(d0[0], d1[0]);
        C.y = pack2(d0[1], d1[1]);
        stA[t] = A; stB[t] = B; stC[t] = C;
        stD[t] = pack2(d0[2], d1[2]);
    }

    // ---- I-side constants: IK points per lane (warp covers 64) ----
    unsigned long long MX[IK], MY[IK], MZ[IK], WP[IK];
    unsigned long long Q0[IK], Q1[IK], Q2[IK];
    float im0[IK], im1[IK], im2[IK];
#pragma unroll
    for (int k = 0; k < IK; k++) {
        const int idx = b * PP + ci * CH + w * (IK * 32) + k * 32 + lane;
        const float* P = pts + idx * 3;
        float ax = P[0], ay = P[1], az = P[2];
        float wp = ax * ax + ay * ay + az * az;
        float e0 = 2.f * (nx[0] * ax + ny[0] * ay + nz[0] * az + nc[0]);
        float e1 = 2.f * (nx[1] * ax + ny[1] * ay + nz[1] * az + nc[1]);
        float e2 = 2.f * (nx[2] * ax + ny[2] * ay + nz[2] * az + nc[2]);
        MX[k] = pack2(-2.f * ax, -2.f * ax);
        MY[k] = pack2(-2.f * ay, -2.f * ay);
        MZ[k] = pack2(-2.f * az, -2.f * az);
        WP[k] = pack2(wp, wp);
        Q0[k] = pack2(e0, e0);     // (2dp)*(2dq) = 4 dp dq
        Q1[k] = pack2(e1, e1);
        Q2[k] = pack2(e2, e2);
        im0[k] = im1[k] = im2[k] = CUDART_INF_F;
    }

    __syncthreads();

    // ---- load this lane's 4 permanent slots into registers ----
    unsigned long long jAx[4], jAy[4], jBx[4], jBy[4], jCx[4], jCy[4], jD[4];
    float jm0a[4], jm0b[4], jm1a[4], jm1b[4], jm2a[4], jm2b[4];
#pragma unroll
    for (int s = 0; s < 4; s++) {
        const int slot = s * 32 + lane;
        ulonglong2 A = stA[slot], B = stB[slot], C = stC[slot];
        jAx[s] = A.x; jAy[s] = A.y; jBx[s] = B.x; jBy[s] = B.y;
        jCx[s] = C.x; jCy[s] = C.y; jD[s] = stD[slot];
        jm0a[s] = jm0b[s] = CUDART_INF_F;
        jm1a[s] = jm1b[s] = CUDART_INF_F;
        jm2a[s] = jm2b[s] = CUDART_INF_F;
    }

    // ---- main loop: 32 ring rotations of the I-side ----
    for (int r = 0; r < 32; r++) {
#pragma unroll
        for (int s = 0; s < 4; s++) {
#pragma unroll
            for (int k = 0; k < IK; k++) {
                unsigned long long acc = fma2(MX[k], jAx[s], add2(jBy[s], WP[k]));
                acc = fma2(MY[k], jAy[s], acc);
                acc = fma2(MZ[k], jBx[s], acc);
                unsigned long long v0 = fma2(Q0[k], jCx[s], acc);
                unsigned long long v1 = fma2(Q1[k], jCy[s], acc);
                unsigned long long v2 = fma2(Q2[k], jD[s],  acc);
                float a0, b0, a1, b1, a2, b2;
                unpack2(v0, a0, b0);
                unpack2(v1, a1, b1);
                unpack2(v2, a2, b2);
                im0[k] = fminf(im0[k], fminf(a0, b0));
                im1[k] = fminf(im1[k], fminf(a1, b1));
                im2[k] = fminf(im2[k], fminf(a2, b2));
                jm0a[s] = fminf(jm0a[s], a0);  jm0b[s] = fminf(jm0b[s], b0);
                jm1a[s] = fminf(jm1a[s], a1);  jm1b[s] = fminf(jm1b[s], b1);
                jm2a[s] = fminf(jm2a[s], a2);  jm2b[s] = fminf(jm2b[s], b2);
            }
        }
        // ring-shuffle I constants + I mins to next lane (32 steps = identity)
        const int src = (lane + 1) & 31;
#pragma unroll
        for (int k = 0; k < IK; k++) {
            MX[k] = __shfl_sync(0xffffffffu, MX[k], src);
            MY[k] = __shfl_sync(0xffffffffu, MY[k], src);
            MZ[k] = __shfl_sync(0xffffffffu, MZ[k], src);
            WP[k] = __shfl_sync(0xffffffffu, WP[k], src);
            Q0[k] = __shfl_sync(0xffffffffu, Q0[k], src);
            Q1[k] = __shfl_sync(0xffffffffu, Q1[k], src);
            Q2[k] = __shfl_sync(0xffffffffu, Q2[k], src);
            im0[k] = __shfl_sync(0xffffffffu, im0[k], src);
            im1[k] = __shfl_sync(0xffffffffu, im1[k], src);
            im2[k] = __shfl_sync(0xffffffffu, im2[k], src);
        }
    }

    // ---- I-side epilogue (data is back home after 32 rotations) ----
#pragma unroll
    for (int k = 0; k < IK; k++) {
        const int idx = b * PP + ci * CH + w * (IK * 32) + k * 32 + lane;
        atomicMin(&g_minbits[0 * NPTS + idx], __float_as_uint(fmaxf(im0[k], 0.f)));
        atomicMin(&g_minbits[1 * NPTS + idx], __float_as_uint(fmaxf(im1[k], 0.f)));
        atomicMin(&g_minbits[2 * NPTS + idx], __float_as_uint(fmaxf(im2[k], 0.f)));
    }

    // ---- J-side: merge 4 warps in smem, then one atomic set per j-point ----
#pragma unroll
    for (int s = 0; s < 4; s++) {
        float* dst = &sJm[w][lane][s * 6];
        dst[0] = jm0a[s]; dst[1] = jm0b[s];
        dst[2] = jm1a[s]; dst[3] = jm1b[s];
        dst[4] = jm2a[s]; dst[5] = jm2b[s];
    }
    __syncthreads();

    // thread t merges slot t (= s*32+l -> owner lane l, group s)
    {
        const int s = t >> 5, l = t & 31;
        float v[6];
#pragma unroll
        for (int i = 0; i < 6; i++) {
            float m = fminf(fminf(sJm[0][l][s * 6 + i], sJm[1][l][s * 6 + i]),
                            fminf(sJm[2][l][s * 6 + i], sJm[3][l][s * 6 + i]));
            v[i] = fmaxf(m, 0.f);
        }
        const int j0 = b * PP + cj * CH + 2 * t;
        atomicMin(&g_minbits[0 * NPTS + j0],     __float_as_uint(v[0]));
        atomicMin(&g_minbits[0 * NPTS + j0 + 1], __float_as_uint(v[1]));
        atomicMin(&g_minbits[1 * NPTS + j0],     __float_as_uint(v[2]));
        atomicMin(&g_minbits[1 * NPTS + j0 + 1], __float_as_uint(v[3]));
        atomicMin(&g_minbits[2 * NPTS + j0],     __float_as_uint(v[4]));
        atomicMin(&g_minbits[2 * NPTS + j0 + 1], __float_as_uint(v[5]));
    }
}

// ---------------------------------------------------------------------------
__global__ __launch_bounds__(256)
void combine_kernel() {
    __shared__ float red[256];
    const int i = blockIdx.x * 256 + threadIdx.x;

    float s = __uint_as_float(g_minbits[0 * NPTS + i])
            + __uint_as_float(g_minbits[1 * NPTS + i])
            + __uint_as_float(g_minbits[2 * NPTS + i]);

    red[threadIdx.x] = s;
    __syncthreads();
#pragma unroll
    for (int off = 128; off > 0; off >>= 1) {
        if (threadIdx.x < off) red[threadIdx.x] += red[threadIdx.x + off];
        __syncthreads();
    }
    if (threadIdx.x == 0) g_partial[blockIdx.x] = red[0];
}

__global__ __launch_bounds__(128)
void finalize_kernel(const float* __restrict__ planes,
                     float* __restrict__ out) {
    __shared__ float red[128];
    __shared__ float regs[BB];
    const int t = threadIdx.x;

    red[t] = g_partial[t];
    __syncthreads();
#pragma unroll
    for (int off = 64; off > 0; off >>= 1) {
        if (t < off) red[t] += red[t + off];
        __syncthreads();
    }

    if (t < BB) {
        float nx[HH], ny[HH], nz[HH], nc[HH];
        load_normals(planes, t, nx, ny, nz, nc);
        float acc = 0.0f;
#pragma unroll
        for (int i = 0; i < HH; i++)
#pragma unroll
            for (int j = 0; j < HH; j++) {
                float g = nx[i] * nx[j] + ny[i] * ny[j] + nz[i] * nz[j]
                        - (i == j ? 1.0f : 0.0f);
                acc += g * g;
            }
        regs[t] = sqrtf(acc);
    }
    __syncthreads();

    if (t == 0) {
        float reg = 0.0f;
#pragma unroll
        for (int b = 0; b < BB; b++) reg += regs[b];
        float refl = 2.0f * red[0] / (float)(BB * PP);  // cham_x == cham_y
        out[0] = refl + 25.0f * reg;
    }
}

// ---------------------------------------------------------------------------
extern "C" void kernel_launch(void* const* d_in, const int* in_sizes, int n_in,
                              void* d_out, int out_size) {
    const float* planes = (const float*)d_in[0];   // (8, 3, 4)
    const float* pts    = (const float*)d_in[1];   // (8, 4096, 3)
    // d_in[2], d_in[3] unused by the reference.

    void* mb = nullptr;
    cudaGetSymbolAddress(&mb, g_minbits);
    cudaMemsetAsync(mb, 0x7F, (size_t)HH * NPTS * sizeof(unsigned int));

    dim3 grid(BLKB, 1, BB);   // 136 x 8 = 1088 blocks
    chamfer_kernel<<<grid, TP>>>(planes, pts);

    combine_kernel<<<NBLK, 256>>>();
    finalize_kernel<<<1, 128>>>(planes, (float*)d_out);
}